// round 1
// baseline (speedup 1.0000x reference)
#include <cuda_runtime.h>
#include <cuda_bf16.h>
#include <cstdint>

// ---------------- problem constants ----------------
#define BATCH 2
#define SEQ   1024
#define DMODEL 768
#define FFDIM 3072
#define NHEAD 12
#define HDIM  64
#define NLAYER 4
#define VOCAB 50257
#define ROWS (BATCH*SEQ)        // 2048

// ---------------- scratch (no allocations allowed) ----------------
__device__ float g_x  [ROWS*DMODEL];   // residual stream
__device__ float g_h  [ROWS*DMODEL];   // layernorm output
__device__ float g_qkv[ROWS*3*DMODEL]; // qkv projections
__device__ float g_o  [ROWS*DMODEL];   // attention output
__device__ float g_ff [ROWS*FFDIM];    // mlp hidden

// ---------------- embedding ----------------
__global__ void embed_kernel(const int* __restrict__ tok,
                             const float* __restrict__ te,
                             const float* __restrict__ pe,
                             float* __restrict__ x) {
    int idx = blockIdx.x * blockDim.x + threadIdx.x;
    if (idx >= ROWS * DMODEL) return;
    int row = idx / DMODEL;
    int d   = idx % DMODEL;
    int s   = row % SEQ;
    x[idx] = te[(size_t)tok[row] * DMODEL + d] + pe[(size_t)s * DMODEL + d];
}

// ---------------- layernorm (one block per row) ----------------
__global__ void ln_kernel(const float* __restrict__ x,
                          const float* __restrict__ g,
                          const float* __restrict__ b,
                          float* __restrict__ y) {
    int row = blockIdx.x;
    const float* xr = x + (size_t)row * DMODEL;
    __shared__ float red[256];
    int tid = threadIdx.x;

    float s = 0.f;
    for (int i = tid; i < DMODEL; i += 256) s += xr[i];
    red[tid] = s; __syncthreads();
    for (int k = 128; k > 0; k >>= 1) {
        if (tid < k) red[tid] += red[tid + k];
        __syncthreads();
    }
    float mean = red[0] * (1.0f / DMODEL);
    __syncthreads();

    float v = 0.f;
    for (int i = tid; i < DMODEL; i += 256) { float d = xr[i] - mean; v += d * d; }
    red[tid] = v; __syncthreads();
    for (int k = 128; k > 0; k >>= 1) {
        if (tid < k) red[tid] += red[tid + k];
        __syncthreads();
    }
    float rstd = rsqrtf(red[0] * (1.0f / DMODEL) + 1e-5f);

    float* yr = y + (size_t)row * DMODEL;
    for (int i = tid; i < DMODEL; i += 256)
        yr[i] = (xr[i] - mean) * rstd * g[i] + b[i];
}

// ---------------- attention (one block per (b,h,q)) ----------------
__global__ void attn_kernel(const float* __restrict__ qkv, float* __restrict__ o) {
    int qi = blockIdx.x;           // 0..SEQ-1
    int h  = blockIdx.y;           // 0..NHEAD-1
    int b  = blockIdx.z;           // 0..BATCH-1
    int row = b * SEQ + qi;
    int tid = threadIdx.x;         // 128 threads

    __shared__ float sq[HDIM];
    __shared__ float sc[SEQ];
    __shared__ float red[128];

    const float* qptr = qkv + (size_t)row * (3 * DMODEL) + h * HDIM;
    if (tid < HDIM) sq[tid] = qptr[tid];
    __syncthreads();

    // scores
    for (int k = tid; k < SEQ; k += 128) {
        const float* kptr = qkv + (size_t)(b * SEQ + k) * (3 * DMODEL) + DMODEL + h * HDIM;
        float s = 0.f;
#pragma unroll
        for (int d = 0; d < HDIM; d++) s += sq[d] * kptr[d];
        sc[k] = s * 0.125f;   // 1/sqrt(64)
    }
    __syncthreads();

    // max
    float m = -1e30f;
    for (int k = tid; k < SEQ; k += 128) m = fmaxf(m, sc[k]);
    red[tid] = m; __syncthreads();
    for (int s2 = 64; s2 > 0; s2 >>= 1) {
        if (tid < s2) red[tid] = fmaxf(red[tid], red[tid + s2]);
        __syncthreads();
    }
    m = red[0];
    __syncthreads();

    // exp + sum
    float sum = 0.f;
    for (int k = tid; k < SEQ; k += 128) {
        float e = __expf(sc[k] - m);
        sc[k] = e;
        sum += e;
    }
    red[tid] = sum; __syncthreads();
    for (int s2 = 64; s2 > 0; s2 >>= 1) {
        if (tid < s2) red[tid] += red[tid + s2];
        __syncthreads();
    }
    float inv = 1.0f / red[0];
    __syncthreads();

    // output: threads split (d, key-half)
    int d    = tid & 63;
    int half = tid >> 6;
    float acc = 0.f;
    const float* vbase = qkv + 2 * DMODEL + h * HDIM + d;
    for (int k = half * (SEQ / 2); k < (half + 1) * (SEQ / 2); k++)
        acc += sc[k] * vbase[(size_t)(b * SEQ + k) * (3 * DMODEL)];
    red[tid] = acc; __syncthreads();
    if (tid < HDIM)
        o[(size_t)row * DMODEL + h * HDIM + tid] = (red[tid] + red[tid + 64]) * inv;
}

// ---------------- SGEMM with epilogues ----------------
// C[M,N] = A[M,K] @ B[K,N]  (+ bias)  (+gelu)  (+residual)
// EPI: 0 = +bias, 1 = +bias+gelu, 2 = +bias+residual, 3 = plain
__device__ __forceinline__ float gelu_tanh(float x) {
    const float c = 0.7978845608028654f; // sqrt(2/pi)
    float x3 = x * x * x;
    return 0.5f * x * (1.0f + tanhf(c * (x + 0.044715f * x3)));
}

template<int EPI>
__global__ void sgemm_kernel(int M, int N, int K,
                             const float* __restrict__ A,
                             const float* __restrict__ B,
                             const float* __restrict__ bias,
                             const float* __restrict__ resid,
                             float* __restrict__ C) {
    constexpr int BM = 128, BN = 128, BK = 8, TM = 8, TN = 8;
    __shared__ float As[BK][BM];
    __shared__ float Bs[BK][BN];

    int t = threadIdx.x;               // 256
    int blockM = blockIdx.y * BM;
    int blockN = blockIdx.x * BN;
    int tr = t / 16, tc = t % 16;      // 16x16 thread grid, each 8x8

    float acc[TM][TN];
#pragma unroll
    for (int i = 0; i < TM; i++)
#pragma unroll
        for (int j = 0; j < TN; j++) acc[i][j] = 0.f;

    int aRow = t >> 1;                  // 0..127
    int aCol = (t & 1) * 4;             // 0 or 4
    int bRow = t >> 5;                  // 0..7
    int bCol = (t & 31) * 4;            // 0..124

    for (int ko = 0; ko < K; ko += BK) {
#pragma unroll
        for (int i = 0; i < 4; i++)
            As[aCol + i][aRow] = A[(size_t)(blockM + aRow) * K + ko + aCol + i];
#pragma unroll
        for (int i = 0; i < 4; i++) {
            int col = blockN + bCol + i;
            Bs[bRow][bCol + i] = (col < N) ? B[(size_t)(ko + bRow) * N + col] : 0.f;
        }
        __syncthreads();

        float ra[TM], rb[TN];
#pragma unroll
        for (int k = 0; k < BK; k++) {
#pragma unroll
            for (int i = 0; i < TM; i++) ra[i] = As[k][tr * TM + i];
#pragma unroll
            for (int j = 0; j < TN; j++) rb[j] = Bs[k][tc * TN + j];
#pragma unroll
            for (int i = 0; i < TM; i++)
#pragma unroll
                for (int j = 0; j < TN; j++) acc[i][j] = fmaf(ra[i], rb[j], acc[i][j]);
        }
        __syncthreads();
    }

#pragma unroll
    for (int i = 0; i < TM; i++) {
        int row = blockM + tr * TM + i;
#pragma unroll
        for (int j = 0; j < TN; j++) {
            int col = blockN + tc * TN + j;
            if (col < N) {
                float v = acc[i][j];
                if (EPI != 3) v += bias[col];
                if (EPI == 1) v = gelu_tanh(v);
                if (EPI == 2) v += resid[(size_t)row * N + col];
                C[(size_t)row * N + col] = v;
            }
        }
    }
}

// ---------------- launch ----------------
extern "C" void kernel_launch(void* const* d_in, const int* in_sizes, int n_in,
                              void* d_out, int out_size) {
    const int*   tokens    = (const int*)  d_in[0];
    const float* tok_embed = (const float*)d_in[1];
    const float* pos_embed = (const float*)d_in[2];
    const float* ln1_g = (const float*)d_in[3];
    const float* ln1_b = (const float*)d_in[4];
    const float* qkv_w = (const float*)d_in[5];
    const float* qkv_b = (const float*)d_in[6];
    const float* proj_w = (const float*)d_in[7];
    const float* proj_b = (const float*)d_in[8];
    const float* ln2_g = (const float*)d_in[9];
    const float* ln2_b = (const float*)d_in[10];
    const float* ff1_w = (const float*)d_in[11];
    const float* ff1_b = (const float*)d_in[12];
    const float* ff2_w = (const float*)d_in[13];
    const float* ff2_b = (const float*)d_in[14];
    const float* lm_w  = (const float*)d_in[15];
    float* out = (float*)d_out;

    float *px, *ph, *pqkv, *po, *pff;
    cudaGetSymbolAddress((void**)&px,   g_x);
    cudaGetSymbolAddress((void**)&ph,   g_h);
    cudaGetSymbolAddress((void**)&pqkv, g_qkv);
    cudaGetSymbolAddress((void**)&po,   g_o);
    cudaGetSymbolAddress((void**)&pff,  g_ff);

    embed_kernel<<<(ROWS * DMODEL + 255) / 256, 256>>>(tokens, tok_embed, pos_embed, px);

    for (int l = 0; l < NLAYER; l++) {
        const float* qw = qkv_w + (size_t)l * DMODEL * 3 * DMODEL;
        const float* qb = qkv_b + (size_t)l * 3 * DMODEL;
        const float* pw = proj_w + (size_t)l * DMODEL * DMODEL;
        const float* pb = proj_b + (size_t)l * DMODEL;
        const float* w1 = ff1_w + (size_t)l * DMODEL * FFDIM;
        const float* b1 = ff1_b + (size_t)l * FFDIM;
        const float* w2 = ff2_w + (size_t)l * FFDIM * DMODEL;
        const float* b2 = ff2_b + (size_t)l * DMODEL;

        // ln1
        ln_kernel<<<ROWS, 256>>>(px, ln1_g + l * DMODEL, ln1_b + l * DMODEL, ph);
        // qkv = ln1 @ Wqkv + b   [2048 x 2304]
        sgemm_kernel<0><<<dim3(3 * DMODEL / 128, ROWS / 128), 256>>>(
            ROWS, 3 * DMODEL, DMODEL, ph, qw, qb, nullptr, pqkv);
        // attention
        attn_kernel<<<dim3(SEQ, NHEAD, BATCH), 128>>>(pqkv, po);
        // x += o @ Wp + bp
        sgemm_kernel<2><<<dim3(DMODEL / 128, ROWS / 128), 256>>>(
            ROWS, DMODEL, DMODEL, po, pw, pb, px, px);
        // ln2
        ln_kernel<<<ROWS, 256>>>(px, ln2_g + l * DMODEL, ln2_b + l * DMODEL, ph);
        // ff = gelu(ln2 @ W1 + b1)   [2048 x 3072]
        sgemm_kernel<1><<<dim3(FFDIM / 128, ROWS / 128), 256>>>(
            ROWS, FFDIM, DMODEL, ph, w1, b1, nullptr, pff);
        // x += ff @ W2 + b2
        sgemm_kernel<2><<<dim3(DMODEL / 128, ROWS / 128), 256>>>(
            ROWS, DMODEL, FFDIM, pff, w2, b2, px, px);
    }

    // logits = x @ lm_head_w   [2048 x 50257]
    sgemm_kernel<3><<<dim3((VOCAB + 127) / 128, ROWS / 128), 256>>>(
        ROWS, VOCAB, DMODEL, px, lm_w, nullptr, nullptr, out);
}

// round 5
// speedup vs baseline: 1.2920x; 1.2920x over previous
#include <cuda_runtime.h>
#include <cuda_bf16.h>
#include <cstdint>

// ---------------- problem constants ----------------
#define BATCH 2
#define SEQ   1024
#define DMODEL 768
#define FFDIM 3072
#define NHEAD 12
#define HDIM  64
#define NLAYER 4
#define VOCAB 50257
#define VPAD  50304          // 393*128
#define ROWS (BATCH*SEQ)     // 2048

// ---------------- scratch (__device__ globals; no allocs allowed) ----------------
__device__ float g_x  [ROWS*DMODEL];
__device__ float g_qkv[ROWS*3*DMODEL];
__device__ __nv_bfloat16 g_hhi[ROWS*DMODEL], g_hlo[ROWS*DMODEL];
__device__ __nv_bfloat16 g_ohi[ROWS*DMODEL], g_olo[ROWS*DMODEL];
__device__ __nv_bfloat16 g_fhi[ROWS*FFDIM],  g_flo[ROWS*FFDIM];
__device__ __nv_bfloat16 g_xhi[ROWS*DMODEL], g_xlo[ROWS*DMODEL];
// transposed bf16 weights [Npad, K], hi/lo
__device__ __nv_bfloat16 g_wqkv_hi[NLAYER*3*DMODEL*DMODEL], g_wqkv_lo[NLAYER*3*DMODEL*DMODEL];
__device__ __nv_bfloat16 g_wprj_hi[NLAYER*DMODEL*DMODEL],   g_wprj_lo[NLAYER*DMODEL*DMODEL];
__device__ __nv_bfloat16 g_wff1_hi[NLAYER*FFDIM*DMODEL],    g_wff1_lo[NLAYER*FFDIM*DMODEL];
__device__ __nv_bfloat16 g_wff2_hi[NLAYER*DMODEL*FFDIM],    g_wff2_lo[NLAYER*DMODEL*FFDIM];
__device__ __nv_bfloat16 g_wlm_hi[(size_t)VPAD*DMODEL],     g_wlm_lo[(size_t)VPAD*DMODEL];

// ---------------- helpers ----------------
__device__ __forceinline__ uint32_t smem_u32(const void* p) {
    uint32_t a;
    asm("{ .reg .u64 t; cvta.to.shared.u64 t, %1; cvt.u32.u64 %0, t; }" : "=r"(a) : "l"(p));
    return a;
}
__device__ __forceinline__ float gelu_tanh(float x) {
    const float c = 0.7978845608028654f;
    float x3 = x * x * x;
    return 0.5f * x * (1.0f + tanhf(c * (x + 0.044715f * x3)));
}
__device__ __forceinline__ void split_bf16(float v, __nv_bfloat16& hi, __nv_bfloat16& lo) {
    hi = __float2bfloat16(v);
    lo = __float2bfloat16(v - __bfloat162float(hi));
}

// swizzled smem tile layout: 128 rows x 32 bf16 (4x 16B chunks per row).
// two logical rows share one 128B physical row; chunk XOR'ed by (r/2)&7 -> conflict-free ldmatrix.
__device__ __forceinline__ uint32_t swz(int r, int c) {
    return (uint32_t)((r >> 1) * 128 + (((((r & 1) << 2) | c) ^ ((r >> 1) & 7)) << 4));
}

#define CP_ASYNC(saddr, gptr) \
    asm volatile("cp.async.cg.shared.global [%0], [%1], 16;" :: "r"(saddr), "l"(gptr))
#define CP_COMMIT() asm volatile("cp.async.commit_group;" ::: "memory")
#define CP_WAIT1()  asm volatile("cp.async.wait_group 1;" ::: "memory")
#define CP_WAIT0()  asm volatile("cp.async.wait_group 0;" ::: "memory")

#define LDMX4(r0, r1, r2, r3, addr) \
    asm volatile("ldmatrix.sync.aligned.m8n8.x4.shared.b16 {%0,%1,%2,%3}, [%4];" \
        : "=r"(r0), "=r"(r1), "=r"(r2), "=r"(r3) : "r"(addr))

#define MMA16816(c, a, b) \
    asm volatile("mma.sync.aligned.m16n8k16.row.col.f32.bf16.bf16.f32 " \
        "{%0,%1,%2,%3}, {%4,%5,%6,%7}, {%8,%9}, {%0,%1,%2,%3};" \
        : "+f"((c)[0]), "+f"((c)[1]), "+f"((c)[2]), "+f"((c)[3]) \
        : "r"((a)[0]), "r"((a)[1]), "r"((a)[2]), "r"((a)[3]), "r"((b)[0]), "r"((b)[1]))

#define STAGE_BYTES 32768   // 4 tiles x 8KB
#define DYN_SMEM    65536   // 2 stages

// ---------------- HMMA GEMM: C[2048,N] = A[2048,K] @ B_T[Npad,K]^T ----------------
// hi/lo split fused: acc += Ahi*Bhi + Alo*Bhi + Ahi*Blo
// EPI: 0 = +bias (fp32 out), 1 = +bias+gelu (bf16 hi/lo out), 2 = +bias+resid (fp32 out),
//      3 = plain, col-guarded at Nreal (fp32 out, stride Nreal)
template<int EPI>
__global__ void __launch_bounds__(256, 1)
tc_gemm(const __nv_bfloat16* __restrict__ Ahi, const __nv_bfloat16* __restrict__ Alo,
        const __nv_bfloat16* __restrict__ Bhi, const __nv_bfloat16* __restrict__ Blo,
        const float* __restrict__ bias, const float* __restrict__ resid,
        float* __restrict__ C, __nv_bfloat16* __restrict__ Chi, __nv_bfloat16* __restrict__ Clo,
        int K, int N, int Nreal)
{
    extern __shared__ char smem[];
    uint32_t sb = smem_u32(smem);
    const int tid = threadIdx.x;
    const int lane = tid & 31;
    const int wid = tid >> 5;
    const int wm = wid >> 2;          // 0..1
    const int wn = wid & 3;           // 0..3
    const int blockM = blockIdx.y * 128;
    const int blockN = blockIdx.x * 128;

    const int NC = K >> 5;            // K/32 chunks

    // fill mapping: each thread owns row r = tid/2, 32B (2 chunks) at cbase
    const int fr = tid >> 1;
    const int fc = (tid & 1) * 2;
    const __nv_bfloat16* gAh = Ahi + (size_t)(blockM + fr) * K + fc * 8;
    const __nv_bfloat16* gAl = Alo + (size_t)(blockM + fr) * K + fc * 8;
    const __nv_bfloat16* gBh = Bhi + (size_t)(blockN + fr) * K + fc * 8;
    const __nv_bfloat16* gBl = Blo + (size_t)(blockN + fr) * K + fc * 8;
    const uint32_t so0 = swz(fr, fc), so1 = swz(fr, fc + 1);

    auto issue = [&](int ci, int stage) {
        uint32_t s0 = sb + stage * STAGE_BYTES;
        size_t kb = (size_t)ci * 32;
        CP_ASYNC(s0 +         so0, gAh + kb);     CP_ASYNC(s0 +         so1, gAh + kb + 8);
        CP_ASYNC(s0 +  8192 + so0, gAl + kb);     CP_ASYNC(s0 +  8192 + so1, gAl + kb + 8);
        CP_ASYNC(s0 + 16384 + so0, gBh + kb);     CP_ASYNC(s0 + 16384 + so1, gBh + kb + 8);
        CP_ASYNC(s0 + 24576 + so0, gBl + kb);     CP_ASYNC(s0 + 24576 + so1, gBl + kb + 8);
        CP_COMMIT();
    };

    float acc[4][4][4];
#pragma unroll
    for (int i = 0; i < 4; i++)
#pragma unroll
        for (int j = 0; j < 4; j++)
#pragma unroll
            for (int k = 0; k < 4; k++) acc[i][j][k] = 0.f;

    // ldmatrix address components
    const int arow = wm * 64 + (lane & 15);
    const int ach  = lane >> 4;                              // 0..1
    const int brow = wn * 32 + (lane & 7) + ((lane >> 4) & 1) * 8;
    const int bch  = (lane >> 3) & 1;                        // 0..1

    issue(0, 0);

    for (int ci = 0; ci < NC; ci++) {
        if (ci + 1 < NC) { issue(ci + 1, (ci + 1) & 1); CP_WAIT1(); }
        else             { CP_WAIT0(); }
        __syncthreads();

        uint32_t s0 = sb + (ci & 1) * STAGE_BYTES;
        uint32_t sAh = s0, sAl = s0 + 8192, sBh = s0 + 16384, sBl = s0 + 24576;

#pragma unroll
        for (int ks = 0; ks < 2; ks++) {
            uint32_t ah[4][4], al[4][4], bh[4][2], bl[4][2];
#pragma unroll
            for (int mt = 0; mt < 4; mt++) {
                uint32_t off = swz(arow + mt * 16, ks * 2 + ach);
                LDMX4(ah[mt][0], ah[mt][1], ah[mt][2], ah[mt][3], sAh + off);
                LDMX4(al[mt][0], al[mt][1], al[mt][2], al[mt][3], sAl + off);
            }
#pragma unroll
            for (int p = 0; p < 2; p++) {
                uint32_t off = swz(brow + p * 16, ks * 2 + bch);
                LDMX4(bh[2*p][0], bh[2*p][1], bh[2*p+1][0], bh[2*p+1][1], sBh + off);
                LDMX4(bl[2*p][0], bl[2*p][1], bl[2*p+1][0], bl[2*p+1][1], sBl + off);
            }
#pragma unroll
            for (int mt = 0; mt < 4; mt++)
#pragma unroll
                for (int nt = 0; nt < 4; nt++) {
                    MMA16816(acc[mt][nt], ah[mt], bh[nt]);
                    MMA16816(acc[mt][nt], al[mt], bh[nt]);
                    MMA16816(acc[mt][nt], ah[mt], bl[nt]);
                }
        }
        __syncthreads();
    }

    // ---------------- epilogue (register -> global) ----------------
#pragma unroll
    for (int mt = 0; mt < 4; mt++) {
#pragma unroll
        for (int nt = 0; nt < 4; nt++) {
            int gcol = blockN + wn * 32 + nt * 8 + 2 * (lane & 3);
            float bv0 = 0.f, bv1 = 0.f;
            if (EPI != 3) { bv0 = bias[gcol]; bv1 = bias[gcol + 1]; }
#pragma unroll
            for (int h = 0; h < 2; h++) {
                int grow = blockM + wm * 64 + mt * 16 + (lane >> 2) + h * 8;
                float v0 = acc[mt][nt][2*h + 0] + bv0;
                float v1 = acc[mt][nt][2*h + 1] + bv1;
                if (EPI == 1) {
                    v0 = gelu_tanh(v0); v1 = gelu_tanh(v1);
                    __nv_bfloat16 h0, l0, h1, l1;
                    split_bf16(v0, h0, l0); split_bf16(v1, h1, l1);
                    __nv_bfloat162 th; th.x = h0; th.y = h1;
                    __nv_bfloat162 tl; tl.x = l0; tl.y = l1;
                    *(__nv_bfloat162*)(Chi + (size_t)grow * N + gcol) = th;
                    *(__nv_bfloat162*)(Clo + (size_t)grow * N + gcol) = tl;
                } else if (EPI == 3) {
                    if (gcol     < Nreal) C[(size_t)grow * Nreal + gcol]     = v0;
                    if (gcol + 1 < Nreal) C[(size_t)grow * Nreal + gcol + 1] = v1;
                } else {
                    if (EPI == 2) {
                        float2 rv = *(const float2*)(resid + (size_t)grow * N + gcol);
                        v0 += rv.x; v1 += rv.y;
                    }
                    float2 t; t.x = v0; t.y = v1;
                    *(float2*)(C + (size_t)grow * N + gcol) = t;
                }
            }
        }
    }
}

// ---------------- weight transpose + split:  W[K,N] fp32 -> T[Npad,K] bf16 hi/lo ----------------
__global__ void convT_kernel(const float* __restrict__ W,
                             __nv_bfloat16* __restrict__ Thi, __nv_bfloat16* __restrict__ Tlo,
                             int K, int N) {
    __shared__ float sm[32][33];
    int n0 = blockIdx.x * 32, k0 = blockIdx.y * 32;
    int tx = threadIdx.x, ty = threadIdx.y;
#pragma unroll
    for (int i = 0; i < 4; i++) {
        int k = k0 + ty + i * 8, n = n0 + tx;
        sm[ty + i * 8][tx] = (n < N) ? W[(size_t)k * N + n] : 0.f;
    }
    __syncthreads();
#pragma unroll
    for (int i = 0; i < 4; i++) {
        int n = n0 + ty + i * 8, k = k0 + tx;
        float v = sm[tx][ty + i * 8];
        __nv_bfloat16 h, l; split_bf16(v, h, l);
        Thi[(size_t)n * K + k] = h;
        Tlo[(size_t)n * K + k] = l;
    }
}

// ---------------- activation fp32 -> bf16 hi/lo ----------------
__global__ void convpair_kernel(const float* __restrict__ X,
                                __nv_bfloat16* __restrict__ hi, __nv_bfloat16* __restrict__ lo,
                                int n) {
    int i = blockIdx.x * 256 + threadIdx.x;
    if (i >= n) return;
    __nv_bfloat16 h, l; split_bf16(X[i], h, l);
    hi[i] = h; lo[i] = l;
}

// ---------------- embedding ----------------
__global__ void embed_kernel(const int* __restrict__ tok,
                             const float* __restrict__ te,
                             const float* __restrict__ pe,
                             float* __restrict__ x) {
    int idx = blockIdx.x * blockDim.x + threadIdx.x;
    if (idx >= ROWS * DMODEL) return;
    int row = idx / DMODEL, d = idx % DMODEL, s = row % SEQ;
    x[idx] = te[(size_t)tok[row] * DMODEL + d] + pe[(size_t)s * DMODEL + d];
}

// ---------------- layernorm -> bf16 hi/lo ----------------
__global__ void ln_kernel(const float* __restrict__ x,
                          const float* __restrict__ g, const float* __restrict__ b,
                          __nv_bfloat16* __restrict__ yhi, __nv_bfloat16* __restrict__ ylo) {
    int row = blockIdx.x;
    const float* xr = x + (size_t)row * DMODEL;
    __shared__ float red[256];
    int tid = threadIdx.x;

    float s = 0.f;
    for (int i = tid; i < DMODEL; i += 256) s += xr[i];
    red[tid] = s; __syncthreads();
    for (int k = 128; k > 0; k >>= 1) { if (tid < k) red[tid] += red[tid + k]; __syncthreads(); }
    float mean = red[0] * (1.0f / DMODEL);
    __syncthreads();

    float v = 0.f;
    for (int i = tid; i < DMODEL; i += 256) { float d = xr[i] - mean; v += d * d; }
    red[tid] = v; __syncthreads();
    for (int k = 128; k > 0; k >>= 1) { if (tid < k) red[tid] += red[tid + k]; __syncthreads(); }
    float rstd = rsqrtf(red[0] * (1.0f / DMODEL) + 1e-5f);

    for (int i = tid; i < DMODEL; i += 256) {
        float val = (xr[i] - mean) * rstd * g[i] + b[i];
        __nv_bfloat16 h, l; split_bf16(val, h, l);
        yhi[(size_t)row * DMODEL + i] = h;
        ylo[(size_t)row * DMODEL + i] = l;
    }
}

// ---------------- attention (fp32, one block per (b,h,q)) -> bf16 hi/lo ----------------
__global__ void attn_kernel(const float* __restrict__ qkv,
                            __nv_bfloat16* __restrict__ ohi, __nv_bfloat16* __restrict__ olo) {
    int qi = blockIdx.x, hd = blockIdx.y, b = blockIdx.z;
    int row = b * SEQ + qi;
    int tid = threadIdx.x;

    __shared__ float sq[HDIM];
    __shared__ float sc[SEQ];
    __shared__ float red[128];

    const float* qptr = qkv + (size_t)row * (3 * DMODEL) + hd * HDIM;
    if (tid < HDIM) sq[tid] = qptr[tid];
    __syncthreads();

    for (int k = tid; k < SEQ; k += 128) {
        const float* kptr = qkv + (size_t)(b * SEQ + k) * (3 * DMODEL) + DMODEL + hd * HDIM;
        float s = 0.f;
#pragma unroll
        for (int d = 0; d < HDIM; d++) s += sq[d] * kptr[d];
        sc[k] = s * 0.125f;
    }
    __syncthreads();

    float m = -1e30f;
    for (int k = tid; k < SEQ; k += 128) m = fmaxf(m, sc[k]);
    red[tid] = m; __syncthreads();
    for (int s2 = 64; s2 > 0; s2 >>= 1) { if (tid < s2) red[tid] = fmaxf(red[tid], red[tid + s2]); __syncthreads(); }
    m = red[0];
    __syncthreads();

    float sum = 0.f;
    for (int k = tid; k < SEQ; k += 128) { float e = __expf(sc[k] - m); sc[k] = e; sum += e; }
    red[tid] = sum; __syncthreads();
    for (int s2 = 64; s2 > 0; s2 >>= 1) { if (tid < s2) red[tid] += red[tid + s2]; __syncthreads(); }
    float inv = 1.0f / red[0];
    __syncthreads();

    int d = tid & 63, half = tid >> 6;
    float acc = 0.f;
    const float* vbase = qkv + 2 * DMODEL + hd * HDIM + d;
    for (int k = half * (SEQ / 2); k < (half + 1) * (SEQ / 2); k++)
        acc += sc[k] * vbase[(size_t)(b * SEQ + k) * (3 * DMODEL)];
    red[tid] = acc; __syncthreads();
    if (tid < HDIM) {
        float val = (red[tid] + red[tid + 64]) * inv;
        __nv_bfloat16 h, l; split_bf16(val, h, l);
        ohi[(size_t)row * DMODEL + hd * HDIM + tid] = h;
        olo[(size_t)row * DMODEL + hd * HDIM + tid] = l;
    }
}

// ---------------- launch ----------------
extern "C" void kernel_launch(void* const* d_in, const int* in_sizes, int n_in,
                              void* d_out, int out_size) {
    const int*   tokens    = (const int*)  d_in[0];
    const float* tok_embed = (const float*)d_in[1];
    const float* pos_embed = (const float*)d_in[2];
    const float* ln1_g = (const float*)d_in[3];
    const float* ln1_b = (const float*)d_in[4];
    const float* qkv_w = (const float*)d_in[5];
    const float* qkv_b = (const float*)d_in[6];
    const float* proj_w = (const float*)d_in[7];
    const float* proj_b = (const float*)d_in[8];
    const float* ln2_g = (const float*)d_in[9];
    const float* ln2_b = (const float*)d_in[10];
    const float* ff1_w = (const float*)d_in[11];
    const float* ff1_b = (const float*)d_in[12];
    const float* ff2_w = (const float*)d_in[13];
    const float* ff2_b = (const float*)d_in[14];
    const float* lm_w  = (const float*)d_in[15];
    float* out = (float*)d_out;

    float *px, *pqkv;
    __nv_bfloat16 *phhi, *phlo, *pohi, *polo, *pfhi, *pflo, *pxhi, *pxlo;
    __nv_bfloat16 *wqh, *wql, *wph, *wpl, *w1h, *w1l, *w2h, *w2l, *wlh, *wll;
    cudaGetSymbolAddress((void**)&px,   g_x);
    cudaGetSymbolAddress((void**)&pqkv, g_qkv);
    cudaGetSymbolAddress((void**)&phhi, g_hhi); cudaGetSymbolAddress((void**)&phlo, g_hlo);
    cudaGetSymbolAddress((void**)&pohi, g_ohi); cudaGetSymbolAddress((void**)&polo, g_olo);
    cudaGetSymbolAddress((void**)&pfhi, g_fhi); cudaGetSymbolAddress((void**)&pflo, g_flo);
    cudaGetSymbolAddress((void**)&pxhi, g_xhi); cudaGetSymbolAddress((void**)&pxlo, g_xlo);
    cudaGetSymbolAddress((void**)&wqh, g_wqkv_hi); cudaGetSymbolAddress((void**)&wql, g_wqkv_lo);
    cudaGetSymbolAddress((void**)&wph, g_wprj_hi); cudaGetSymbolAddress((void**)&wpl, g_wprj_lo);
    cudaGetSymbolAddress((void**)&w1h, g_wff1_hi); cudaGetSymbolAddress((void**)&w1l, g_wff1_lo);
    cudaGetSymbolAddress((void**)&w2h, g_wff2_hi); cudaGetSymbolAddress((void**)&w2l, g_wff2_lo);
    cudaGetSymbolAddress((void**)&wlh, g_wlm_hi);  cudaGetSymbolAddress((void**)&wll, g_wlm_lo);

    cudaFuncSetAttribute(tc_gemm<0>, cudaFuncAttributeMaxDynamicSharedMemorySize, DYN_SMEM);
    cudaFuncSetAttribute(tc_gemm<1>, cudaFuncAttributeMaxDynamicSharedMemorySize, DYN_SMEM);
    cudaFuncSetAttribute(tc_gemm<2>, cudaFuncAttributeMaxDynamicSharedMemorySize, DYN_SMEM);
    cudaFuncSetAttribute(tc_gemm<3>, cudaFuncAttributeMaxDynamicSharedMemorySize, DYN_SMEM);

    dim3 tb(32, 8);
    // weight conversions (transpose + hi/lo split)
    for (int l = 0; l < NLAYER; l++) {
        convT_kernel<<<dim3(3 * DMODEL / 32, DMODEL / 32), tb>>>(
            qkv_w + (size_t)l * DMODEL * 3 * DMODEL,
            wqh + (size_t)l * 3 * DMODEL * DMODEL, wql + (size_t)l * 3 * DMODEL * DMODEL,
            DMODEL, 3 * DMODEL);
        convT_kernel<<<dim3(DMODEL / 32, DMODEL / 32), tb>>>(
            proj_w + (size_t)l * DMODEL * DMODEL,
            wph + (size_t)l * DMODEL * DMODEL, wpl + (size_t)l * DMODEL * DMODEL,
            DMODEL, DMODEL);
        convT_kernel<<<dim3(FFDIM / 32, DMODEL / 32), tb>>>(
            ff1_w + (size_t)l * DMODEL * FFDIM,
            w1h + (size_t)l * FFDIM * DMODEL, w1l + (size_t)l * FFDIM * DMODEL,
            DMODEL, FFDIM);
        convT_kernel<<<dim3(DMODEL / 32, FFDIM / 32), tb>>>(
            ff2_w + (size_t)l * FFDIM * DMODEL,
            w2h + (size_t)l * DMODEL * FFDIM, w2l + (size_t)l * DMODEL * FFDIM,
            FFDIM, DMODEL);
    }
    convT_kernel<<<dim3(VPAD / 32, DMODEL / 32), tb>>>(lm_w, wlh, wll, DMODEL, VOCAB);

    embed_kernel<<<(ROWS * DMODEL + 255) / 256, 256>>>(tokens, tok_embed, pos_embed, px);

    for (int l = 0; l < NLAYER; l++) {
        const float* qb = qkv_b + (size_t)l * 3 * DMODEL;
        const float* pb = proj_b + (size_t)l * DMODEL;
        const float* b1 = ff1_b + (size_t)l * FFDIM;
        const float* b2 = ff2_b + (size_t)l * DMODEL;

        ln_kernel<<<ROWS, 256>>>(px, ln1_g + l * DMODEL, ln1_b + l * DMODEL, phhi, phlo);
        tc_gemm<0><<<dim3(3 * DMODEL / 128, ROWS / 128), 256, DYN_SMEM>>>(
            phhi, phlo,
            wqh + (size_t)l * 3 * DMODEL * DMODEL, wql + (size_t)l * 3 * DMODEL * DMODEL,
            qb, nullptr, pqkv, nullptr, nullptr, DMODEL, 3 * DMODEL, 3 * DMODEL);
        attn_kernel<<<dim3(SEQ, NHEAD, BATCH), 128>>>(pqkv, pohi, polo);
        tc_gemm<2><<<dim3(DMODEL / 128, ROWS / 128), 256, DYN_SMEM>>>(
            pohi, polo,
            wph + (size_t)l * DMODEL * DMODEL, wpl + (size_t)l * DMODEL * DMODEL,
            pb, px, px, nullptr, nullptr, DMODEL, DMODEL, DMODEL);
        ln_kernel<<<ROWS, 256>>>(px, ln2_g + l * DMODEL, ln2_b + l * DMODEL, phhi, phlo);
        tc_gemm<1><<<dim3(FFDIM / 128, ROWS / 128), 256, DYN_SMEM>>>(
            phhi, phlo,
            w1h + (size_t)l * FFDIM * DMODEL, w1l + (size_t)l * FFDIM * DMODEL,
            b1, nullptr, nullptr, pfhi, pflo, DMODEL, FFDIM, FFDIM);
        tc_gemm<2><<<dim3(DMODEL / 128, ROWS / 128), 256, DYN_SMEM>>>(
            pfhi, pflo,
            w2h + (size_t)l * DMODEL * FFDIM, w2l + (size_t)l * DMODEL * FFDIM,
            b2, px, px, nullptr, nullptr, FFDIM, DMODEL, DMODEL);
    }

    convpair_kernel<<<(ROWS * DMODEL + 255) / 256, 256>>>(px, pxhi, pxlo, ROWS * DMODEL);
    tc_gemm<3><<<dim3(VPAD / 128, ROWS / 128), 256, DYN_SMEM>>>(
        pxhi, pxlo, wlh, wll,
        nullptr, nullptr, out, nullptr, nullptr, DMODEL, VPAD, VOCAB);
}

// round 6
// speedup vs baseline: 1.2949x; 1.0023x over previous
#include <cuda_runtime.h>
#include <cuda_bf16.h>
#include <cstdint>

// ---------------- problem constants ----------------
#define BATCH 2
#define SEQ   1024
#define DMODEL 768
#define FFDIM 3072
#define NHEAD 12
#define HDIM  64
#define NLAYER 4
#define VOCAB 50257
#define VPAD  50304          // 393*128
#define ROWS (BATCH*SEQ)     // 2048

// ---------------- scratch (__device__ globals; no allocs allowed) ----------------
__device__ float g_x  [ROWS*DMODEL];
__device__ float g_qkv[ROWS*3*DMODEL];
__device__ __nv_bfloat16 g_hhi[ROWS*DMODEL], g_hlo[ROWS*DMODEL];
__device__ __nv_bfloat16 g_ohi[ROWS*DMODEL], g_olo[ROWS*DMODEL];
__device__ __nv_bfloat16 g_fhi[ROWS*FFDIM],  g_flo[ROWS*FFDIM];
__device__ __nv_bfloat16 g_xhi[ROWS*DMODEL], g_xlo[ROWS*DMODEL];
// transposed bf16 weights [Npad, K], hi/lo
__device__ __nv_bfloat16 g_wqkv_hi[NLAYER*3*DMODEL*DMODEL], g_wqkv_lo[NLAYER*3*DMODEL*DMODEL];
__device__ __nv_bfloat16 g_wprj_hi[NLAYER*DMODEL*DMODEL],   g_wprj_lo[NLAYER*DMODEL*DMODEL];
__device__ __nv_bfloat16 g_wff1_hi[NLAYER*FFDIM*DMODEL],    g_wff1_lo[NLAYER*FFDIM*DMODEL];
__device__ __nv_bfloat16 g_wff2_hi[NLAYER*DMODEL*FFDIM],    g_wff2_lo[NLAYER*DMODEL*FFDIM];
__device__ __nv_bfloat16 g_wlm_hi[(size_t)VPAD*DMODEL],     g_wlm_lo[(size_t)VPAD*DMODEL];

// ---------------- helpers ----------------
__device__ __forceinline__ uint32_t smem_u32(const void* p) {
    uint32_t a;
    asm("{ .reg .u64 t; cvta.to.shared.u64 t, %1; cvt.u32.u64 %0, t; }" : "=r"(a) : "l"(p));
    return a;
}
__device__ __forceinline__ float gelu_tanh(float x) {
    const float c = 0.7978845608028654f;
    float x3 = x * x * x;
    return 0.5f * x * (1.0f + tanhf(c * (x + 0.044715f * x3)));
}
__device__ __forceinline__ void split_bf16(float v, __nv_bfloat16& hi, __nv_bfloat16& lo) {
    hi = __float2bfloat16(v);
    lo = __float2bfloat16(v - __bfloat162float(hi));
}

// swizzled smem tile layout: 128 rows x 32 bf16 (4x 16B chunks per row).
// two logical rows share one 128B physical row; chunk XOR'ed by (r/2)&7 -> conflict-free ldmatrix.
__device__ __forceinline__ uint32_t swz(int r, int c) {
    return (uint32_t)((r >> 1) * 128 + (((((r & 1) << 2) | c) ^ ((r >> 1) & 7)) << 4));
}

#define CP_ASYNC(saddr, gptr) \
    asm volatile("cp.async.cg.shared.global [%0], [%1], 16;" :: "r"(saddr), "l"(gptr))
#define CP_COMMIT() asm volatile("cp.async.commit_group;" ::: "memory")
#define CP_WAIT1()  asm volatile("cp.async.wait_group 1;" ::: "memory")
#define CP_WAIT0()  asm volatile("cp.async.wait_group 0;" ::: "memory")

#define LDMX4(r0, r1, r2, r3, addr) \
    asm volatile("ldmatrix.sync.aligned.m8n8.x4.shared.b16 {%0,%1,%2,%3}, [%4];" \
        : "=r"(r0), "=r"(r1), "=r"(r2), "=r"(r3) : "r"(addr))

#define MMA16816(c, a, b) \
    asm volatile("mma.sync.aligned.m16n8k16.row.col.f32.bf16.bf16.f32 " \
        "{%0,%1,%2,%3}, {%4,%5,%6,%7}, {%8,%9}, {%0,%1,%2,%3};" \
        : "+f"((c)[0]), "+f"((c)[1]), "+f"((c)[2]), "+f"((c)[3]) \
        : "r"((a)[0]), "r"((a)[1]), "r"((a)[2]), "r"((a)[3]), "r"((b)[0]), "r"((b)[1]))

#define STAGE_BYTES 32768   // 4 tiles x 8KB
#define NSTAGE      3
#define DYN_SMEM    (STAGE_BYTES * NSTAGE)   // 98304

// ---------------- HMMA GEMM: C[2048,N] = A[2048,K] @ B_T[Npad,K]^T ----------------
// hi/lo split fused: acc += Ahi*Bhi + Alo*Bhi + Ahi*Blo
// EPI: 0 = +bias (fp32 out), 1 = +bias+gelu (bf16 hi/lo out), 2 = +bias+resid (fp32 out),
//      3 = plain, col-guarded at Nreal (fp32 out, stride Nreal)
template<int EPI>
__global__ void __launch_bounds__(256, 1)
tc_gemm(const __nv_bfloat16* __restrict__ Ahi, const __nv_bfloat16* __restrict__ Alo,
        const __nv_bfloat16* __restrict__ Bhi, const __nv_bfloat16* __restrict__ Blo,
        const float* __restrict__ bias, const float* __restrict__ resid,
        float* __restrict__ C, __nv_bfloat16* __restrict__ Chi, __nv_bfloat16* __restrict__ Clo,
        int K, int N, int Nreal)
{
    extern __shared__ char smem[];
    uint32_t sb = smem_u32(smem);
    const int tid = threadIdx.x;
    const int lane = tid & 31;
    const int wid = tid >> 5;
    const int wm = wid >> 2;          // 0..1
    const int wn = wid & 3;           // 0..3
    const int blockM = blockIdx.y * 128;
    const int blockN = blockIdx.x * 128;

    const int NC = K >> 5;            // K/32 chunks

    // fill mapping: each thread owns row r = tid/2, 32B (2 chunks)
    const int fr = tid >> 1;
    const int fc = (tid & 1) * 2;
    const __nv_bfloat16* gAh = Ahi + (size_t)(blockM + fr) * K + fc * 8;
    const __nv_bfloat16* gAl = Alo + (size_t)(blockM + fr) * K + fc * 8;
    const __nv_bfloat16* gBh = Bhi + (size_t)(blockN + fr) * K + fc * 8;
    const __nv_bfloat16* gBl = Blo + (size_t)(blockN + fr) * K + fc * 8;
    const uint32_t so0 = swz(fr, fc), so1 = swz(fr, fc + 1);

    auto issue = [&](int ci) {
        uint32_t s0 = sb + (uint32_t)(ci % NSTAGE) * STAGE_BYTES;
        size_t kb = (size_t)ci * 32;
        CP_ASYNC(s0 +         so0, gAh + kb);     CP_ASYNC(s0 +         so1, gAh + kb + 8);
        CP_ASYNC(s0 +  8192 + so0, gAl + kb);     CP_ASYNC(s0 +  8192 + so1, gAl + kb + 8);
        CP_ASYNC(s0 + 16384 + so0, gBh + kb);     CP_ASYNC(s0 + 16384 + so1, gBh + kb + 8);
        CP_ASYNC(s0 + 24576 + so0, gBl + kb);     CP_ASYNC(s0 + 24576 + so1, gBl + kb + 8);
        CP_COMMIT();
    };

    float acc[4][4][4];
#pragma unroll
    for (int i = 0; i < 4; i++)
#pragma unroll
        for (int j = 0; j < 4; j++)
#pragma unroll
            for (int k = 0; k < 4; k++) acc[i][j][k] = 0.f;

    // ldmatrix address components
    const int arow = wm * 64 + (lane & 15);
    const int ach  = lane >> 4;                              // 0..1
    const int brow = wn * 32 + (lane & 7) + ((lane >> 4) & 1) * 8;
    const int bch  = (lane >> 3) & 1;                        // 0..1

    issue(0);
    issue(1);

    for (int ci = 0; ci < NC; ci++) {
        if (ci + 1 < NC) CP_WAIT1(); else CP_WAIT0();
        __syncthreads();
        if (ci + 2 < NC) issue(ci + 2);

        uint32_t s0 = sb + (uint32_t)(ci % NSTAGE) * STAGE_BYTES;
        uint32_t sAh = s0, sAl = s0 + 8192, sBh = s0 + 16384, sBl = s0 + 24576;

#pragma unroll
        for (int ks = 0; ks < 2; ks++) {
            uint32_t ah[4][4], al[4][4], bh[4][2], bl[4][2];
#pragma unroll
            for (int mt = 0; mt < 4; mt++) {
                uint32_t off = swz(arow + mt * 16, ks * 2 + ach);
                LDMX4(ah[mt][0], ah[mt][1], ah[mt][2], ah[mt][3], sAh + off);
                LDMX4(al[mt][0], al[mt][1], al[mt][2], al[mt][3], sAl + off);
            }
#pragma unroll
            for (int p = 0; p < 2; p++) {
                uint32_t off = swz(brow + p * 16, ks * 2 + bch);
                LDMX4(bh[2*p][0], bh[2*p][1], bh[2*p+1][0], bh[2*p+1][1], sBh + off);
                LDMX4(bl[2*p][0], bl[2*p][1], bl[2*p+1][0], bl[2*p+1][1], sBl + off);
            }
#pragma unroll
            for (int mt = 0; mt < 4; mt++)
#pragma unroll
                for (int nt = 0; nt < 4; nt++) {
                    MMA16816(acc[mt][nt], ah[mt], bh[nt]);
                    MMA16816(acc[mt][nt], al[mt], bh[nt]);
                    MMA16816(acc[mt][nt], ah[mt], bl[nt]);
                }
        }
    }

    // ---------------- epilogue (register -> global) ----------------
#pragma unroll
    for (int mt = 0; mt < 4; mt++) {
#pragma unroll
        for (int nt = 0; nt < 4; nt++) {
            int gcol = blockN + wn * 32 + nt * 8 + 2 * (lane & 3);
            float bv0 = 0.f, bv1 = 0.f;
            if (EPI != 3) { bv0 = bias[gcol]; bv1 = bias[gcol + 1]; }
#pragma unroll
            for (int h = 0; h < 2; h++) {
                int grow = blockM + wm * 64 + mt * 16 + (lane >> 2) + h * 8;
                float v0 = acc[mt][nt][2*h + 0] + bv0;
                float v1 = acc[mt][nt][2*h + 1] + bv1;
                if (EPI == 1) {
                    v0 = gelu_tanh(v0); v1 = gelu_tanh(v1);
                    __nv_bfloat16 h0, l0, h1, l1;
                    split_bf16(v0, h0, l0); split_bf16(v1, h1, l1);
                    __nv_bfloat162 th; th.x = h0; th.y = h1;
                    __nv_bfloat162 tl; tl.x = l0; tl.y = l1;
                    *(__nv_bfloat162*)(Chi + (size_t)grow * N + gcol) = th;
                    *(__nv_bfloat162*)(Clo + (size_t)grow * N + gcol) = tl;
                } else if (EPI == 3) {
                    if (gcol     < Nreal) C[(size_t)grow * Nreal + gcol]     = v0;
                    if (gcol + 1 < Nreal) C[(size_t)grow * Nreal + gcol + 1] = v1;
                } else {
                    if (EPI == 2) {
                        float2 rv = *(const float2*)(resid + (size_t)grow * N + gcol);
                        v0 += rv.x; v1 += rv.y;
                    }
                    float2 t; t.x = v0; t.y = v1;
                    *(float2*)(C + (size_t)grow * N + gcol) = t;
                }
            }
        }
    }
}

// ---------------- weight transpose + split:  W[K,N] fp32 -> T[Npad,K] bf16 hi/lo ----------------
__global__ void convT_kernel(const float* __restrict__ W,
                             __nv_bfloat16* __restrict__ Thi, __nv_bfloat16* __restrict__ Tlo,
                             int K, int N) {
    __shared__ float sm[32][33];
    int n0 = blockIdx.x * 32, k0 = blockIdx.y * 32;
    int tx = threadIdx.x, ty = threadIdx.y;
#pragma unroll
    for (int i = 0; i < 4; i++) {
        int k = k0 + ty + i * 8, n = n0 + tx;
        sm[ty + i * 8][tx] = (n < N) ? W[(size_t)k * N + n] : 0.f;
    }
    __syncthreads();
#pragma unroll
    for (int i = 0; i < 4; i++) {
        int n = n0 + ty + i * 8, k = k0 + tx;
        float v = sm[tx][ty + i * 8];
        __nv_bfloat16 h, l; split_bf16(v, h, l);
        Thi[(size_t)n * K + k] = h;
        Tlo[(size_t)n * K + k] = l;
    }
}

// ---------------- activation fp32 -> bf16 hi/lo ----------------
__global__ void convpair_kernel(const float* __restrict__ X,
                                __nv_bfloat16* __restrict__ hi, __nv_bfloat16* __restrict__ lo,
                                int n) {
    int i = blockIdx.x * 256 + threadIdx.x;
    if (i >= n) return;
    __nv_bfloat16 h, l; split_bf16(X[i], h, l);
    hi[i] = h; lo[i] = l;
}

// ---------------- embedding ----------------
__global__ void embed_kernel(const int* __restrict__ tok,
                             const float* __restrict__ te,
                             const float* __restrict__ pe,
                             float* __restrict__ x) {
    int idx = blockIdx.x * blockDim.x + threadIdx.x;
    if (idx >= ROWS * DMODEL) return;
    int row = idx / DMODEL, d = idx % DMODEL, s = row % SEQ;
    x[idx] = te[(size_t)tok[row] * DMODEL + d] + pe[(size_t)s * DMODEL + d];
}

// ---------------- layernorm -> bf16 hi/lo ----------------
__global__ void ln_kernel(const float* __restrict__ x,
                          const float* __restrict__ g, const float* __restrict__ b,
                          __nv_bfloat16* __restrict__ yhi, __nv_bfloat16* __restrict__ ylo) {
    int row = blockIdx.x;
    const float* xr = x + (size_t)row * DMODEL;
    __shared__ float red[256];
    int tid = threadIdx.x;

    float s = 0.f;
    for (int i = tid; i < DMODEL; i += 256) s += xr[i];
    red[tid] = s; __syncthreads();
    for (int k = 128; k > 0; k >>= 1) { if (tid < k) red[tid] += red[tid + k]; __syncthreads(); }
    float mean = red[0] * (1.0f / DMODEL);
    __syncthreads();

    float v = 0.f;
    for (int i = tid; i < DMODEL; i += 256) { float d = xr[i] - mean; v += d * d; }
    red[tid] = v; __syncthreads();
    for (int k = 128; k > 0; k >>= 1) { if (tid < k) red[tid] += red[tid + k]; __syncthreads(); }
    float rstd = rsqrtf(red[0] * (1.0f / DMODEL) + 1e-5f);

    for (int i = tid; i < DMODEL; i += 256) {
        float val = (xr[i] - mean) * rstd * g[i] + b[i];
        __nv_bfloat16 h, l; split_bf16(val, h, l);
        yhi[(size_t)row * DMODEL + i] = h;
        ylo[(size_t)row * DMODEL + i] = l;
    }
}

// ---------------- attention (fp32, one block per (b,h,q)) -> bf16 hi/lo ----------------
__global__ void attn_kernel(const float* __restrict__ qkv,
                            __nv_bfloat16* __restrict__ ohi, __nv_bfloat16* __restrict__ olo) {
    int qi = blockIdx.x, hd = blockIdx.y, b = blockIdx.z;
    int row = b * SEQ + qi;
    int tid = threadIdx.x;

    __shared__ float sq[HDIM];
    __shared__ float sc[SEQ];
    __shared__ float red[128];

    const float* qptr = qkv + (size_t)row * (3 * DMODEL) + hd * HDIM;
    if (tid < HDIM) sq[tid] = qptr[tid];
    __syncthreads();

    for (int k = tid; k < SEQ; k += 128) {
        const float* kptr = qkv + (size_t)(b * SEQ + k) * (3 * DMODEL) + DMODEL + hd * HDIM;
        float s = 0.f;
#pragma unroll
        for (int d = 0; d < HDIM; d++) s += sq[d] * kptr[d];
        sc[k] = s * 0.125f;
    }
    __syncthreads();

    float m = -1e30f;
    for (int k = tid; k < SEQ; k += 128) m = fmaxf(m, sc[k]);
    red[tid] = m; __syncthreads();
    for (int s2 = 64; s2 > 0; s2 >>= 1) { if (tid < s2) red[tid] = fmaxf(red[tid], red[tid + s2]); __syncthreads(); }
    m = red[0];
    __syncthreads();

    float sum = 0.f;
    for (int k = tid; k < SEQ; k += 128) { float e = __expf(sc[k] - m); sc[k] = e; sum += e; }
    red[tid] = sum; __syncthreads();
    for (int s2 = 64; s2 > 0; s2 >>= 1) { if (tid < s2) red[tid] += red[tid + s2]; __syncthreads(); }
    float inv = 1.0f / red[0];
    __syncthreads();

    int d = tid & 63, half = tid >> 6;
    float acc = 0.f;
    const float* vbase = qkv + 2 * DMODEL + hd * HDIM + d;
    for (int k = half * (SEQ / 2); k < (half + 1) * (SEQ / 2); k++)
        acc += sc[k] * vbase[(size_t)(b * SEQ + k) * (3 * DMODEL)];
    red[tid] = acc; __syncthreads();
    if (tid < HDIM) {
        float val = (red[tid] + red[tid + 64]) * inv;
        __nv_bfloat16 h, l; split_bf16(val, h, l);
        ohi[(size_t)row * DMODEL + hd * HDIM + tid] = h;
        olo[(size_t)row * DMODEL + hd * HDIM + tid] = l;
    }
}

// ---------------- launch ----------------
extern "C" void kernel_launch(void* const* d_in, const int* in_sizes, int n_in,
                              void* d_out, int out_size) {
    const int*   tokens    = (const int*)  d_in[0];
    const float* tok_embed = (const float*)d_in[1];
    const float* pos_embed = (const float*)d_in[2];
    const float* ln1_g = (const float*)d_in[3];
    const float* ln1_b = (const float*)d_in[4];
    const float* qkv_w = (const float*)d_in[5];
    const float* qkv_b = (const float*)d_in[6];
    const float* proj_w = (const float*)d_in[7];
    const float* proj_b = (const float*)d_in[8];
    const float* ln2_g = (const float*)d_in[9];
    const float* ln2_b = (const float*)d_in[10];
    const float* ff1_w = (const float*)d_in[11];
    const float* ff1_b = (const float*)d_in[12];
    const float* ff2_w = (const float*)d_in[13];
    const float* ff2_b = (const float*)d_in[14];
    const float* lm_w  = (const float*)d_in[15];
    float* out = (float*)d_out;

    float *px, *pqkv;
    __nv_bfloat16 *phhi, *phlo, *pohi, *polo, *pfhi, *pflo, *pxhi, *pxlo;
    __nv_bfloat16 *wqh, *wql, *wph, *wpl, *w1h, *w1l, *w2h, *w2l, *wlh, *wll;
    cudaGetSymbolAddress((void**)&px,   g_x);
    cudaGetSymbolAddress((void**)&pqkv, g_qkv);
    cudaGetSymbolAddress((void**)&phhi, g_hhi); cudaGetSymbolAddress((void**)&phlo, g_hlo);
    cudaGetSymbolAddress((void**)&pohi, g_ohi); cudaGetSymbolAddress((void**)&polo, g_olo);
    cudaGetSymbolAddress((void**)&pfhi, g_fhi); cudaGetSymbolAddress((void**)&pflo, g_flo);
    cudaGetSymbolAddress((void**)&pxhi, g_xhi); cudaGetSymbolAddress((void**)&pxlo, g_xlo);
    cudaGetSymbolAddress((void**)&wqh, g_wqkv_hi); cudaGetSymbolAddress((void**)&wql, g_wqkv_lo);
    cudaGetSymbolAddress((void**)&wph, g_wprj_hi); cudaGetSymbolAddress((void**)&wpl, g_wprj_lo);
    cudaGetSymbolAddress((void**)&w1h, g_wff1_hi); cudaGetSymbolAddress((void**)&w1l, g_wff1_lo);
    cudaGetSymbolAddress((void**)&w2h, g_wff2_hi); cudaGetSymbolAddress((void**)&w2l, g_wff2_lo);
    cudaGetSymbolAddress((void**)&wlh, g_wlm_hi);  cudaGetSymbolAddress((void**)&wll, g_wlm_lo);

    cudaFuncSetAttribute(tc_gemm<0>, cudaFuncAttributeMaxDynamicSharedMemorySize, DYN_SMEM);
    cudaFuncSetAttribute(tc_gemm<1>, cudaFuncAttributeMaxDynamicSharedMemorySize, DYN_SMEM);
    cudaFuncSetAttribute(tc_gemm<2>, cudaFuncAttributeMaxDynamicSharedMemorySize, DYN_SMEM);
    cudaFuncSetAttribute(tc_gemm<3>, cudaFuncAttributeMaxDynamicSharedMemorySize, DYN_SMEM);

    dim3 tb(32, 8);

    // --- layer 0, ordered so launch #6 (ncu -s 5 -c 1) is the qkv tc_gemm ---
    // 1: embed
    embed_kernel<<<(ROWS * DMODEL + 255) / 256, 256>>>(tokens, tok_embed, pos_embed, px);
    // 2-4: layer-0 weight conversions needed before first gemms
    convT_kernel<<<dim3(3 * DMODEL / 32, DMODEL / 32), tb>>>(
        qkv_w, wqh, wql, DMODEL, 3 * DMODEL);
    convT_kernel<<<dim3(DMODEL / 32, DMODEL / 32), tb>>>(
        proj_w, wph, wpl, DMODEL, DMODEL);
    convT_kernel<<<dim3(FFDIM / 32, DMODEL / 32), tb>>>(
        ff1_w, w1h, w1l, DMODEL, FFDIM);
    // 5: ln1
    ln_kernel<<<ROWS, 256>>>(px, ln1_g, ln1_b, phhi, phlo);
    // 6: qkv gemm  <-- profiled launch
    tc_gemm<0><<<dim3(3 * DMODEL / 128, ROWS / 128), 256, DYN_SMEM>>>(
        phhi, phlo, wqh, wql, qkv_b, nullptr, pqkv, nullptr, nullptr,
        DMODEL, 3 * DMODEL, 3 * DMODEL);
    // 7: attention
    attn_kernel<<<dim3(SEQ, NHEAD, BATCH), 128>>>(pqkv, pohi, polo);
    // 8: proj gemm (+resid)
    tc_gemm<2><<<dim3(DMODEL / 128, ROWS / 128), 256, DYN_SMEM>>>(
        pohi, polo, wph, wpl, proj_b, px, px, nullptr, nullptr,
        DMODEL, DMODEL, DMODEL);
    // 9: ln2
    ln_kernel<<<ROWS, 256>>>(px, ln2_g, ln2_b, phhi, phlo);
    // 10: ff1 gemm (+gelu)
    tc_gemm<1><<<dim3(FFDIM / 128, ROWS / 128), 256, DYN_SMEM>>>(
        phhi, phlo, w1h, w1l, ff1_b, nullptr, nullptr, pfhi, pflo,
        DMODEL, FFDIM, FFDIM);
    // 11: layer-0 ff2 conversion
    convT_kernel<<<dim3(DMODEL / 32, FFDIM / 32), tb>>>(
        ff2_w, w2h, w2l, FFDIM, DMODEL);
    // 12: ff2 gemm (+resid)
    tc_gemm<2><<<dim3(DMODEL / 128, ROWS / 128), 256, DYN_SMEM>>>(
        pfhi, pflo, w2h, w2l, ff2_b, px, px, nullptr, nullptr,
        FFDIM, DMODEL, DMODEL);

    // --- remaining weight conversions (layers 1..3 + lm head) ---
    for (int l = 1; l < NLAYER; l++) {
        convT_kernel<<<dim3(3 * DMODEL / 32, DMODEL / 32), tb>>>(
            qkv_w + (size_t)l * DMODEL * 3 * DMODEL,
            wqh + (size_t)l * 3 * DMODEL * DMODEL, wql + (size_t)l * 3 * DMODEL * DMODEL,
            DMODEL, 3 * DMODEL);
        convT_kernel<<<dim3(DMODEL / 32, DMODEL / 32), tb>>>(
            proj_w + (size_t)l * DMODEL * DMODEL,
            wph + (size_t)l * DMODEL * DMODEL, wpl + (size_t)l * DMODEL * DMODEL,
            DMODEL, DMODEL);
        convT_kernel<<<dim3(FFDIM / 32, DMODEL / 32), tb>>>(
            ff1_w + (size_t)l * DMODEL * FFDIM,
            w1h + (size_t)l * FFDIM * DMODEL, w1l + (size_t)l * FFDIM * DMODEL,
            DMODEL, FFDIM);
        convT_kernel<<<dim3(DMODEL / 32, FFDIM / 32), tb>>>(
            ff2_w + (size_t)l * FFDIM * DMODEL,
            w2h + (size_t)l * DMODEL * FFDIM, w2l + (size_t)l * DMODEL * FFDIM,
            FFDIM, DMODEL);
    }
    convT_kernel<<<dim3(VPAD / 32, DMODEL / 32), tb>>>(lm_w, wlh, wll, DMODEL, VOCAB);

    // --- layers 1..3 ---
    for (int l = 1; l < NLAYER; l++) {
        const float* qb = qkv_b + (size_t)l * 3 * DMODEL;
        const float* pb = proj_b + (size_t)l * DMODEL;
        const float* b1 = ff1_b + (size_t)l * FFDIM;
        const float* b2 = ff2_b + (size_t)l * DMODEL;

        ln_kernel<<<ROWS, 256>>>(px, ln1_g + l * DMODEL, ln1_b + l * DMODEL, phhi, phlo);
        tc_gemm<0><<<dim3(3 * DMODEL / 128, ROWS / 128), 256, DYN_SMEM>>>(
            phhi, phlo,
            wqh + (size_t)l * 3 * DMODEL * DMODEL, wql + (size_t)l * 3 * DMODEL * DMODEL,
            qb, nullptr, pqkv, nullptr, nullptr, DMODEL, 3 * DMODEL, 3 * DMODEL);
        attn_kernel<<<dim3(SEQ, NHEAD, BATCH), 128>>>(pqkv, pohi, polo);
        tc_gemm<2><<<dim3(DMODEL / 128, ROWS / 128), 256, DYN_SMEM>>>(
            pohi, polo,
            wph + (size_t)l * DMODEL * DMODEL, wpl + (size_t)l * DMODEL * DMODEL,
            pb, px, px, nullptr, nullptr, DMODEL, DMODEL, DMODEL);
        ln_kernel<<<ROWS, 256>>>(px, ln2_g + l * DMODEL, ln2_b + l * DMODEL, phhi, phlo);
        tc_gemm<1><<<dim3(FFDIM / 128, ROWS / 128), 256, DYN_SMEM>>>(
            phhi, phlo,
            w1h + (size_t)l * FFDIM * DMODEL, w1l + (size_t)l * FFDIM * DMODEL,
            b1, nullptr, nullptr, pfhi, pflo, DMODEL, FFDIM, FFDIM);
        tc_gemm<2><<<dim3(DMODEL / 128, ROWS / 128), 256, DYN_SMEM>>>(
            pfhi, pflo,
            w2h + (size_t)l * DMODEL * FFDIM, w2l + (size_t)l * DMODEL * FFDIM,
            b2, px, px, nullptr, nullptr, FFDIM, DMODEL, DMODEL);
    }

    convpair_kernel<<<(ROWS * DMODEL + 255) / 256, 256>>>(px, pxhi, pxlo, ROWS * DMODEL);
    tc_gemm<3><<<dim3(VPAD / 128, ROWS / 128), 256, DYN_SMEM>>>(
        pxhi, pxlo, wlh, wll,
        nullptr, nullptr, out, nullptr, nullptr, DMODEL, VPAD, VOCAB);
}